// round 1
// baseline (speedup 1.0000x reference)
#include <cuda_runtime.h>

#define NT 256

// Shared-memory arena layout (floats):
//   [0,     6144)  qkv  (3 x 16 x 128)
//   [6144,  8192)  o    (16 x 128)          (also final-reduce scratch)
//   [8192, 10240)  h    (16 x 128)
//   [10240,18432)  ff   (16 x 512)          (also xs: 16 x 196 padded to stride 200)
//   [18432,20480)  x1/x2 (16 x 128)
#define ARENA_FLOATS 20480
#define OFF_QKV 0
#define OFF_O   6144
#define OFF_H   8192
#define OFF_FF  10240
#define OFF_X1  18432

__device__ __forceinline__ void warp_reduce2(float& s, float& s2) {
    #pragma unroll
    for (int off = 16; off; off >>= 1) {
        s  += __shfl_xor_sync(0xffffffffu, s,  off);
        s2 += __shfl_xor_sync(0xffffffffu, s2, off);
    }
}

// LayerNorm over 16 rows x 128 cols. src/resid/dst are 16x128 (stride 128).
// dst = (dst_add ? dst_add : 0) + LN(src [+ resid]) * g + b
__device__ void lnorm(const float* __restrict__ src, const float* __restrict__ resid,
                      const float* __restrict__ g, const float* __restrict__ b,
                      float* __restrict__ dst, const float* __restrict__ dst_add) {
    int warp = threadIdx.x >> 5, lane = threadIdx.x & 31;
    for (int r = warp; r < 16; r += NT / 32) {
        float v[4]; float s = 0.f, s2 = 0.f;
        #pragma unroll
        for (int i = 0; i < 4; i++) {
            int c = lane + 32 * i;
            float x = src[r * 128 + c];
            if (resid) x += resid[r * 128 + c];
            v[i] = x; s += x; s2 += x * x;
        }
        warp_reduce2(s, s2);
        float m   = s * (1.f / 128.f);
        float var = fmaxf(s2 * (1.f / 128.f) - m * m, 0.f);
        float inv = rsqrtf(var + 1e-5f);
        #pragma unroll
        for (int i = 0; i < 4; i++) {
            int c = lane + 32 * i;
            float val = (v[i] - m) * inv * g[c] + b[c];
            if (dst_add) val += dst_add[r * 128 + c];
            dst[r * 128 + c] = val;
        }
    }
}

// QKV: in (16 x K, smem stride XST) times three (K x 128) weights -> qkv (3 x 16 x 128)
template<int K, int XST>
__device__ void qkv_gemm(const float* __restrict__ in,
                         const float* __restrict__ wq, const float* __restrict__ wk,
                         const float* __restrict__ wv, float* __restrict__ qkv) {
    for (int idx = threadIdx.x; idx < 384; idx += NT) {
        int e = idx & 127, m = idx >> 7;
        const float* W = (m == 0) ? wq : (m == 1) ? wk : wv;
        float acc[16];
        #pragma unroll
        for (int r = 0; r < 16; r++) acc[r] = 0.f;
        #pragma unroll 2
        for (int c = 0; c < K; c += 4) {
            float w0 = W[(c + 0) * 128 + e];
            float w1 = W[(c + 1) * 128 + e];
            float w2 = W[(c + 2) * 128 + e];
            float w3 = W[(c + 3) * 128 + e];
            #pragma unroll
            for (int r = 0; r < 16; r++) {
                float4 x = *reinterpret_cast<const float4*>(&in[r * XST + c]);
                acc[r] += x.x * w0 + x.y * w1 + x.z * w2 + x.w * w3;
            }
        }
        float* op = qkv + m * 2048;
        #pragma unroll
        for (int r = 0; r < 16; r++) op[r * 128 + e] = acc[r];
    }
}

// out (16 x N) = in (16 x K, stride K) @ W (K x N) + bias, optional relu
template<int K>
__device__ void gemm_cols(const float* __restrict__ in, const float* __restrict__ W, int N,
                          const float* __restrict__ bias, float* __restrict__ out, bool relu) {
    for (int e = threadIdx.x; e < N; e += NT) {
        float acc[16];
        #pragma unroll
        for (int r = 0; r < 16; r++) acc[r] = 0.f;
        #pragma unroll 2
        for (int c = 0; c < K; c += 4) {
            float w0 = W[(c + 0) * N + e];
            float w1 = W[(c + 1) * N + e];
            float w2 = W[(c + 2) * N + e];
            float w3 = W[(c + 3) * N + e];
            #pragma unroll
            for (int r = 0; r < 16; r++) {
                float4 x = *reinterpret_cast<const float4*>(&in[r * K + c]);
                acc[r] += x.x * w0 + x.y * w1 + x.z * w2 + x.w * w3;
            }
        }
        float bb = bias[e];
        #pragma unroll
        for (int r = 0; r < 16; r++) {
            float v = acc[r] + bb;
            out[r * N + e] = relu ? fmaxf(v, 0.f) : v;
        }
    }
}

// out (16 x 128) = in (16 x K) @ W (K x 128) + bias; 2 threads per column (8 rows each)
template<int K>
__device__ void gemm_half(const float* __restrict__ in, const float* __restrict__ W,
                          const float* __restrict__ bias, float* __restrict__ out) {
    int e = threadIdx.x & 127, half = threadIdx.x >> 7;
    const float* xr = in + half * 8 * K;
    float acc[8];
    #pragma unroll
    for (int r = 0; r < 8; r++) acc[r] = 0.f;
    #pragma unroll 2
    for (int c = 0; c < K; c += 4) {
        float w0 = W[(c + 0) * 128 + e];
        float w1 = W[(c + 1) * 128 + e];
        float w2 = W[(c + 2) * 128 + e];
        float w3 = W[(c + 3) * 128 + e];
        #pragma unroll
        for (int r = 0; r < 8; r++) {
            float4 x = *reinterpret_cast<const float4*>(&xr[r * K + c]);
            acc[r] += x.x * w0 + x.y * w1 + x.z * w2 + x.w * w3;
        }
    }
    float bb = bias[e];
    #pragma unroll
    for (int r = 0; r < 8; r++) out[(half * 8 + r) * 128 + e] = acc[r] + bb;
}

// Attention: 64 heads, head_dim 2, 16 tokens. qkv = [q|k|v] each 16x128.
__device__ void attention(const float* __restrict__ qkv, float* __restrict__ o) {
    const float* q = qkv;
    const float* k = qkv + 2048;
    const float* v = qkv + 4096;
    const float scale = 0.7071067811865475f; // 1/sqrt(2)
    for (int idx = threadIdx.x; idx < 1024; idx += NT) {
        int hh = idx & 63, qr = idx >> 6;
        float q0 = q[qr * 128 + 2 * hh], q1 = q[qr * 128 + 2 * hh + 1];
        float s[16], mx = -1e30f;
        #pragma unroll
        for (int j = 0; j < 16; j++) {
            s[j] = (q0 * k[j * 128 + 2 * hh] + q1 * k[j * 128 + 2 * hh + 1]) * scale;
            mx = fmaxf(mx, s[j]);
        }
        float sum = 0.f;
        #pragma unroll
        for (int j = 0; j < 16; j++) { s[j] = __expf(s[j] - mx); sum += s[j]; }
        float inv = 1.f / sum;
        float o0 = 0.f, o1 = 0.f;
        #pragma unroll
        for (int j = 0; j < 16; j++) {
            o0 += s[j] * v[j * 128 + 2 * hh];
            o1 += s[j] * v[j * 128 + 2 * hh + 1];
        }
        o[qr * 128 + 2 * hh]     = o0 * inv;
        o[qr * 128 + 2 * hh + 1] = o1 * inv;
    }
}

// One transformer block. in: 16 x K (stride XST). dst = (dst_add?:0) + block(in).
template<int K, int XST>
__device__ void tblock(float* arena, const float* __restrict__ in, bool has_res,
                       const float* __restrict__ wq, const float* __restrict__ wk,
                       const float* __restrict__ wv, const float* __restrict__ wo,
                       const float* __restrict__ bo,
                       const float* __restrict__ ff1, const float* __restrict__ bf1,
                       const float* __restrict__ ff2, const float* __restrict__ bf2,
                       const float* __restrict__ g1, const float* __restrict__ b1,
                       const float* __restrict__ g2, const float* __restrict__ b2,
                       float* __restrict__ dst, const float* __restrict__ dst_add) {
    float* qkv = arena + OFF_QKV;
    float* o   = arena + OFF_O;
    float* h   = arena + OFF_H;
    float* ff  = arena + OFF_FF;

    qkv_gemm<K, XST>(in, wq, wk, wv, qkv);
    __syncthreads();
    attention(qkv, o);
    __syncthreads();
    gemm_half<128>(o, wo, bo, h);          // h <- o @ wo + bo
    __syncthreads();
    lnorm(h, has_res ? in : nullptr, g1, b1, h, nullptr);   // h <- LN(h [+ in])
    __syncthreads();
    gemm_cols<128>(h, ff1, 512, bf1, ff, true);   // ff <- relu(h @ ff1 + bf1)
    __syncthreads();
    gemm_half<512>(ff, ff2, bf2, o);       // o <- ff @ ff2 + bf2
    __syncthreads();
    lnorm(o, h, g2, b2, dst, dst_add);     // dst <- [dst_add +] LN(o + h)
    __syncthreads();
}

__global__ void __launch_bounds__(NT, 2)
encoder_kernel(const float* __restrict__ enc, const float* __restrict__ off,
               const float* __restrict__ b1_wq, const float* __restrict__ b1_wk,
               const float* __restrict__ b1_wv, const float* __restrict__ b1_wo,
               const float* __restrict__ b1_bo,
               const float* __restrict__ b1_ff1, const float* __restrict__ b1_bf1,
               const float* __restrict__ b1_ff2, const float* __restrict__ b1_bf2,
               const float* __restrict__ b1_g1, const float* __restrict__ b1_b1,
               const float* __restrict__ b1_g2, const float* __restrict__ b1_b2,
               const float* __restrict__ b2_wq, const float* __restrict__ b2_wk,
               const float* __restrict__ b2_wv, const float* __restrict__ b2_wo,
               const float* __restrict__ b2_bo,
               const float* __restrict__ b2_ff1, const float* __restrict__ b2_bf1,
               const float* __restrict__ b2_ff2, const float* __restrict__ b2_bf2,
               const float* __restrict__ b2_g1, const float* __restrict__ b2_b1,
               const float* __restrict__ b2_g2, const float* __restrict__ b2_b2,
               const float* __restrict__ wf, const float* __restrict__ bf,
               float* __restrict__ out) {
    extern __shared__ float arena[];
    const int n = blockIdx.x;
    const int b = n >> 7;      // batch
    const int t = n & 127;     // time

    // ---- build windowed input xs: 16 x 196 (stride 200), edge-clamped in time ----
    float* xs = arena + OFF_FF;   // aliases ff region (dead until FF1 of block1)
    for (int i = threadIdx.x; i < 16 * 196; i += NT) {
        int w = i / 196, c = i - w * 196;
        int tc = t + w - 8;
        tc = min(max(tc, 0), 127);
        float val = (c < 112) ? enc[((long)b * 112 + c) * 128 + tc]
                              : off[b * 84 + (c - 112)];
        xs[w * 200 + c] = val;
    }
    __syncthreads();

    float* x1 = arena + OFF_X1;

    // block1: CIN=196 -> 128, no residual into first LN
    tblock<196, 200>(arena, xs, false,
                     b1_wq, b1_wk, b1_wv, b1_wo, b1_bo,
                     b1_ff1, b1_bf1, b1_ff2, b1_bf2,
                     b1_g1, b1_b1, b1_g2, b1_b2,
                     x1, nullptr);

    // block2: 128 -> 128 with residual; x2 = x1 + block2(x1) written in place
    tblock<128, 128>(arena, x1, true,
                     b2_wq, b2_wk, b2_wv, b2_wo, b2_bo,
                     b2_ff1, b2_bf1, b2_ff2, b2_bf2,
                     b2_g1, b2_b1, b2_g2, b2_b2,
                     x1, x1);

    // ---- final projection: y[e] = x2.flat(2048) @ wf[:,e] + bf[e] ----
    int e = threadIdx.x & 127, part = threadIdx.x >> 7;
    float acc = 0.f;
    const float* xv  = x1 + part * 1024;
    const float* wfp = wf + (long)part * 1024 * 128 + e;
    #pragma unroll 2
    for (int c = 0; c < 1024; c += 4) {
        float4 x = *reinterpret_cast<const float4*>(&xv[c]);
        acc += x.x * wfp[(c + 0) * 128] + x.y * wfp[(c + 1) * 128]
             + x.z * wfp[(c + 2) * 128] + x.w * wfp[(c + 3) * 128];
    }
    float* red = arena + OFF_O;
    if (part == 1) red[e] = acc;
    __syncthreads();
    if (part == 0) out[((long)b * 128 + e) * 128 + t] = acc + red[e] + bf[e];
}

extern "C" void kernel_launch(void* const* d_in, const int* in_sizes, int n_in,
                              void* d_out, int out_size) {
    (void)in_sizes; (void)n_in; (void)out_size;
    const float* enc = (const float*)d_in[0];
    const float* off = (const float*)d_in[1];
    const float* p[30];
    for (int i = 0; i < 30; i++) p[i] = (const float*)d_in[i];

    static bool attr_set = false;
    if (!attr_set) {
        cudaFuncSetAttribute(encoder_kernel,
                             cudaFuncAttributeMaxDynamicSharedMemorySize,
                             ARENA_FLOATS * (int)sizeof(float));
        attr_set = true;
    }

    encoder_kernel<<<64 * 128, NT, ARENA_FLOATS * sizeof(float)>>>(
        enc, off,
        p[2], p[3], p[4], p[5], p[6], p[7], p[8], p[9], p[10],
        p[11], p[12], p[13], p[14],
        p[15], p[16], p[17], p[18], p[19], p[20], p[21], p[22], p[23],
        p[24], p[25], p[26], p[27],
        p[28], p[29],
        (float*)d_out);
}